// round 17
// baseline (speedup 1.0000x reference)
#include <cuda_runtime.h>
#include <math.h>

#define Nx   256
#define BN   2048      // 8*256

// ---------------- scratch ----------------
__device__ float g_A [BN*128];   // h @ Wm1[0:128]
__device__ float g_Bm[BN*128];   // h @ Wm1[128:256]
__device__ float g_as[BN];
__device__ float g_bs[BN];
__device__ float g_M [128*128];  // Wm2 @ Wu_bot
__device__ float g_vb[128];      // bm2 @ Wu_bot + bu

typedef unsigned long long u64;

__device__ __forceinline__ u64 dup2(float a) {
    u64 r; unsigned au = __float_as_uint(a);
    asm("mov.b64 %0, {%1, %1};" : "=l"(r) : "r"(au));
    return r;
}
__device__ __forceinline__ u64 add2v(u64 a, u64 b) {
    u64 r; asm("add.rn.f32x2 %0, %1, %2;" : "=l"(r) : "l"(a), "l"(b));
    return r;
}
__device__ __forceinline__ u64 fma2v(u64 a, u64 b, u64 c) {
    u64 r; asm("fma.rn.f32x2 %0, %1, %2, %3;" : "=l"(r) : "l"(a), "l"(b), "l"(c));
    return r;
}
__device__ __forceinline__ void fma2a(u64& acc, u64 a, u64 b) {
    asm("fma.rn.f32x2 %0, %1, %2, %0;" : "+l"(acc) : "l"(a), "l"(b));
}
__device__ __forceinline__ float2 unpk(u64 v) {
    unsigned lo, hi;
    asm("mov.b64 {%0, %1}, %2;" : "=r"(lo), "=r"(hi) : "l"(v));
    return make_float2(__uint_as_float(lo), __uint_as_float(hi));
}
__device__ __forceinline__ u64 pack2(float x, float y) {
    u64 r;
    asm("mov.b64 %0, {%1, %2};" : "=l"(r)
        : "r"(__float_as_uint(x)), "r"(__float_as_uint(y)));
    return r;
}
__device__ __forceinline__ u64 relu2(u64 v) {
    float2 f = unpk(v);
    return pack2(fmaxf(f.x, 0.f), fmaxf(f.y, 0.f));
}

// =======================================================================
// Stage 1 (R2-proven, verbatim): grid 141, block 256
// =======================================================================
__global__ void __launch_bounds__(256) k_stage1(
    const float* __restrict__ h,   const float* __restrict__ Wm1,
    const float* __restrict__ Wa,  const float* __restrict__ Wm2,
    const float* __restrict__ bm2, const float* __restrict__ Wu,
    const float* __restrict__ bu)
{
    const int bid = blockIdx.x;
    const int t   = threadIdx.x;

    if (bid < 132) {
        __shared__ float As[32][68];
        __shared__ float Ws[32][68];
        const float *A, *W;
        float* dst;
        int row0, col0;
        if (bid < 128) {
            int mt = bid >> 2, nt = bid & 3;
            row0 = mt * 64;
            A = h;
            W = Wm1 + (nt >= 2 ? 128*128 : 0);
            col0 = (nt & 1) * 64;
            dst = (nt >= 2) ? g_Bm : g_A;
        } else {
            int bb = bid - 128;
            row0 = (bb >> 1) * 64;
            A = Wm2;
            W = Wu + 128*128;
            col0 = (bb & 1) * 64;
            dst = g_M;
        }
        const int ty = t >> 4, tx = t & 15;
        float acc[4][4];
#pragma unroll
        for (int r = 0; r < 4; r++)
#pragma unroll
            for (int c = 0; c < 4; c++) acc[r][c] = 0.f;

        for (int k0 = 0; k0 < 128; k0 += 32) {
#pragma unroll
            for (int n = 0; n < 2; n++) {
                int l  = t + n*256;
                int r  = l >> 3;
                int kq = (l & 7) * 4;
                float4 v = *(const float4*)&A[(row0 + r)*128 + k0 + kq];
                As[kq+0][r] = v.x; As[kq+1][r] = v.y;
                As[kq+2][r] = v.z; As[kq+3][r] = v.w;
            }
#pragma unroll
            for (int n = 0; n < 2; n++) {
                int l  = t + n*256;
                int wk = l >> 4;
                int wn = (l & 15) * 4;
                *(float4*)&Ws[wk][wn] =
                    *(const float4*)&W[(k0 + wk)*128 + col0 + wn];
            }
            __syncthreads();
#pragma unroll
            for (int kk = 0; kk < 32; kk++) {
                float4 a4 = *(const float4*)&As[kk][ty*4];
                float4 b4 = *(const float4*)&Ws[kk][tx*4];
                acc[0][0] = fmaf(a4.x, b4.x, acc[0][0]);
                acc[0][1] = fmaf(a4.x, b4.y, acc[0][1]);
                acc[0][2] = fmaf(a4.x, b4.z, acc[0][2]);
                acc[0][3] = fmaf(a4.x, b4.w, acc[0][3]);
                acc[1][0] = fmaf(a4.y, b4.x, acc[1][0]);
                acc[1][1] = fmaf(a4.y, b4.y, acc[1][1]);
                acc[1][2] = fmaf(a4.y, b4.z, acc[1][2]);
                acc[1][3] = fmaf(a4.y, b4.w, acc[1][3]);
                acc[2][0] = fmaf(a4.z, b4.x, acc[2][0]);
                acc[2][1] = fmaf(a4.z, b4.y, acc[2][1]);
                acc[2][2] = fmaf(a4.z, b4.z, acc[2][2]);
                acc[2][3] = fmaf(a4.z, b4.w, acc[2][3]);
                acc[3][0] = fmaf(a4.w, b4.x, acc[3][0]);
                acc[3][1] = fmaf(a4.w, b4.y, acc[3][1]);
                acc[3][2] = fmaf(a4.w, b4.z, acc[3][2]);
                acc[3][3] = fmaf(a4.w, b4.w, acc[3][3]);
            }
            __syncthreads();
        }
#pragma unroll
        for (int r = 0; r < 4; r++)
            *(float4*)&dst[(row0 + ty*4 + r)*128 + col0 + tx*4] =
                make_float4(acc[r][0], acc[r][1], acc[r][2], acc[r][3]);

    } else if (bid < 140) {
        __shared__ __align__(16) float was[272];
        for (int k = t; k < 257; k += 256) was[k] = Wa[k];
        __syncthreads();
        const int wrp = t >> 5, lane = t & 31;
        const int rowbase = (bid - 132) * 256 + wrp * 32;
        float4 wa1 = *(const float4*)&was[lane*4];
        float4 wa2 = *(const float4*)&was[128 + lane*4];
        for (int rr = 0; rr < 32; rr++) {
            int row = rowbase + rr;
            float4 hv = *(const float4*)&h[row*128 + lane*4];
            float sa = hv.x*wa1.x + hv.y*wa1.y + hv.z*wa1.z + hv.w*wa1.w;
            float sb = hv.x*wa2.x + hv.y*wa2.y + hv.z*wa2.z + hv.w*wa2.w;
#pragma unroll
            for (int o = 16; o; o >>= 1) {
                sa += __shfl_xor_sync(0xffffffffu, sa, o);
                sb += __shfl_xor_sync(0xffffffffu, sb, o);
            }
            if (lane == 0) { g_as[row] = sa; g_bs[row] = sb; }
        }
    } else {
        if (t < 128) {
            float acc = bu[t];
#pragma unroll 8
            for (int k = 0; k < 128; k++)
                acc = fmaf(bm2[k], Wu[(128 + k)*128 + t], acc);
            g_vb[t] = acc;
        }
    }
}

// =======================================================================
// k_pairout: R16 pair (compaction, 4ch/thread, 8-i) + FUSED epilogue
// grid (32,8), block 512, dyn smem 177216
// =======================================================================
#define PAIR_SMEM ((32768 + 8192 + 2048 + 1024 + 256 + 8 + 8) * 4)

__global__ void __launch_bounds__(512, 1) k_pairout(
    const float* __restrict__ h,
    const float* __restrict__ dist, const int* __restrict__ adj,
    const float* __restrict__ Wm1,  const float* __restrict__ bm1,
    const float* __restrict__ Wa,   const float* __restrict__ ba,
    const float* __restrict__ Wu,
    float* __restrict__ out)
{
    extern __shared__ float sm[];
    float*      Bsh   = sm;                              // [256][128] 128KB
    ulonglong2* recsh = (ulonglong2*)(sm + 32768);       // [8][256] {dd,ww}
    float*      hSsh  = sm + 32768 + 8192;               // [8][256] (= jsh)
    int*        jsh   = (int*)hSsh;                      // [8][256] phase1/2
    float*      Ash   = sm + 32768 + 8192 + 2048;        // [8][128] A+bm1
    float*      bssh  = Ash + 1024;                      // 256
    int*        nnzsh = (int*)(bssh + 256);              // 8
    float*      csh   = bssh + 256 + 8;                  // 8

    const int t = threadIdx.x;
    const int b = blockIdx.y, i0 = blockIdx.x * 8;
    const int lane = t & 31, wrp = t >> 5;

    // ---- small fills
    if (t < 256) bssh[t] = g_bs[b*Nx + t];
#pragma unroll
    for (int k = 0; k < 2; k++) {
        int idx = t + k*512;
        if (idx < 1024)
            Ash[idx] = g_A[(size_t)(b*Nx + i0)*128 + idx] + bm1[idx & 127];
    }
    __syncthreads();

    // ---- phase 1 (warps 0..7) || Bsh fill (warps 8..15)
    if (wrp < 8) {
        const float wa_d = Wa[256];
        const int ig = b*Nx + i0 + wrp;
        const float a_i = g_as[ig] + ba[0];
        float l[8], dv[8]; int mk[8];
#pragma unroll
        for (int jj = 0; jj < 8; jj++) {
            int j = jj*32 + lane;
            float d = dist[(size_t)ig*Nx + j];
            int   m = adj [(size_t)ig*Nx + j];
            float x = fmaf(d, wa_d, a_i + bssh[j]);
            x = (x >= 0.f) ? x : 0.2f * x;
            l[jj] = m ? x : -1e9f;
            dv[jj] = d; mk[jj] = m;
        }
        float mx = l[0];
#pragma unroll
        for (int jj = 1; jj < 8; jj++) mx = fmaxf(mx, l[jj]);
#pragma unroll
        for (int o = 16; o; o >>= 1) mx = fmaxf(mx, __shfl_xor_sync(0xffffffffu, mx, o));
        float sum = 0.f, cs = 0.f;
#pragma unroll
        for (int jj = 0; jj < 8; jj++) {
            float e = expf(l[jj] - mx);
            l[jj] = e; sum += e;
            cs += mk[jj] ? e : 0.f;
        }
#pragma unroll
        for (int o = 16; o; o >>= 1) {
            sum += __shfl_xor_sync(0xffffffffu, sum, o);
            cs  += __shfl_xor_sync(0xffffffffu, cs,  o);
        }
        const float inv = 1.f / sum;
        int nbase = 0;
#pragma unroll
        for (int jj = 0; jj < 8; jj++) {
            unsigned bal = __ballot_sync(0xffffffffu, mk[jj] != 0);
            if (mk[jj]) {
                int pos = nbase + __popc(bal & ((1u << lane) - 1u));
                ulonglong2 rec;
                rec.x = dup2(dv[jj]);
                rec.y = dup2(l[jj] * inv);
                recsh[wrp*256 + pos] = rec;
                jsh  [wrp*256 + pos] = jj*32 + lane;
            }
            nbase += __popc(bal);
        }
        if (lane == 0) { nnzsh[wrp] = nbase; csh[wrp] = cs * inv; }
    } else {
        const float4* src = (const float4*)(g_Bm + (size_t)b*Nx*128);
        float4* d4 = (float4*)Bsh;
        const int tl = t - 256;           // 0..255
#pragma unroll
        for (int k = 0; k < 32; k++) d4[tl + k*256] = src[tl + k*256];
    }
    __syncthreads();

    // ---- phase 2: thread (cp 0..31 -> 4ch, q 0..15 -> j stride)
    const int cp = lane, q = wrp;
    {
        const ulonglong2 wd4 = *(const ulonglong2*)&Wm1[256*128 + cp*4];
        ulonglong2 acc[8];
#pragma unroll
        for (int i = 0; i < 8; i++) { acc[i].x = 0ull; acc[i].y = 0ull; }

#pragma unroll
        for (int i = 0; i < 8; i++) {
            const ulonglong2 av = *(const ulonglong2*)&Ash[i*128 + cp*4];
            const int n = nnzsh[i];
            const ulonglong2* rp = recsh + i*256;
            const int*        jp = jsh   + i*256;
            for (int s = q; s < n; s += 16) {
                int j = jp[s];
                ulonglong2 rec = rp[s];
                ulonglong2 b4 = *(const ulonglong2*)&Bsh[j*128 + cp*4];
                u64 x0 = fma2v(rec.x, wd4.x, add2v(av.x, b4.x));
                u64 x1 = fma2v(rec.x, wd4.y, add2v(av.y, b4.y));
                acc[i].x = fma2v(rec.y, relu2(x0), acc[i].x);
                acc[i].y = fma2v(rec.y, relu2(x1), acc[i].y);
            }
        }
        __syncthreads();   // B reads + jsh reads done

        // partials overlay on Bsh: [8][16][32] ulonglong2 (64KB)
        ulonglong2* part = (ulonglong2*)Bsh;
#pragma unroll
        for (int i = 0; i < 8; i++)
            part[(i*16 + q)*32 + cp] = acc[i];
    }
    __syncthreads();

    // ---- reduce partials -> hSsh[ i ][128..256); h rows -> hSsh[i][0..128)
    {
        ulonglong2* part = (ulonglong2*)Bsh;
        if (t < 256) {
            const int i = t >> 5, cpp = t & 31;
            u64 sx = 0ull, sy = 0ull;
#pragma unroll
            for (int qq = 0; qq < 16; qq++) {
                ulonglong2 v = part[(i*16 + qq)*32 + cpp];
                sx = add2v(sx, v.x); sy = add2v(sy, v.y);
            }
            float2 p = unpk(sx), r = unpk(sy);
            *(float4*)&hSsh[i*256 + 128 + cpp*4] =
                make_float4(p.x, p.y, r.x, r.y);
        } else {
            const int tl = t - 256;
            const int i = tl >> 5, q4 = tl & 31;
            *(float4*)&hSsh[i*256 + q4*4] =
                *(const float4*)&h[(size_t)(b*Nx + i0 + i)*128 + q4*4];
        }
    }
    __syncthreads();    // part fully read; Bsh free for Wcat

    // ---- fill Wcat = [Wu_top ; g_M] into Bsh (256x128)
#pragma unroll
    for (int n = 0; n < 16; n++) {
        int idx = t + n*512;              // 0..8191 float4
        int kk = idx >> 5, c4 = (idx & 31) * 4;
        const float* src = (kk < 128) ? &Wu[(size_t)kk*128 + c4]
                                      : &g_M[(size_t)(kk - 128)*128 + c4];
        *(float4*)&Bsh[kk*128 + c4] = *(const float4*)src;
    }
    __syncthreads();

    // ---- epilogue GEMM: out[8][128] = hS @ Wcat (+ c*vb, relu)
    // thread: kg = t>>8 (K half), row = (t>>5)&7, c4 = lane*4
    {
        const int kg = t >> 8;
        const int row = (t >> 5) & 7;
        const int c4 = lane * 4;
        const float* arow = hSsh + row*256 + kg*128;
        const float* wb   = Bsh + (size_t)kg*128*128 + c4;

        u64 o0 = 0ull, o1 = 0ull;
#pragma unroll 4
        for (int k = 0; k < 128; k++) {
            u64 aa = dup2(arow[k]);                 // bcast LDS.32
            ulonglong2 w2 = *(const ulonglong2*)&wb[k*128];
            fma2a(o0, aa, w2.x);
            fma2a(o1, aa, w2.y);
        }
        // combine K-halves via recsh overlay: [256] ulonglong2
        ulonglong2* p2 = recsh;     // free post-phase2
        if (kg == 1) {
            ulonglong2 v; v.x = o0; v.y = o1;
            p2[(t & 255)] = v;
        }
        __syncthreads();
        if (kg == 0) {
            ulonglong2 v = p2[t];
            o0 = add2v(o0, v.x);
            o1 = add2v(o1, v.y);
            float cr = csh[row];
            float4 vb4 = *(const float4*)&g_vb[c4];
            float2 p = unpk(o0), qv = unpk(o1);
            float4 o;
            o.x = fmaxf(fmaf(cr, vb4.x, p.x),  0.f);
            o.y = fmaxf(fmaf(cr, vb4.y, p.y),  0.f);
            o.z = fmaxf(fmaf(cr, vb4.z, qv.x), 0.f);
            o.w = fmaxf(fmaf(cr, vb4.w, qv.y), 0.f);
            *(float4*)&out[(size_t)(b*Nx + i0 + row)*128 + c4] = o;
        }
    }
}

// =======================================================================
extern "C" void kernel_launch(void* const* d_in, const int* in_sizes, int n_in,
                              void* d_out, int out_size)
{
    const float* h    = (const float*)d_in[0];
    const int*   adj  = (const int*)  d_in[1];
    const float* dist = (const float*)d_in[2];
    const float* Wm1  = (const float*)d_in[3];
    const float* bm1  = (const float*)d_in[4];
    const float* Wm2  = (const float*)d_in[5];
    const float* bm2  = (const float*)d_in[6];
    const float* Wa   = (const float*)d_in[7];
    const float* ba   = (const float*)d_in[8];
    const float* Wu   = (const float*)d_in[9];
    const float* bu   = (const float*)d_in[10];
    float* out = (float*)d_out;

    cudaFuncSetAttribute(k_pairout, cudaFuncAttributeMaxDynamicSharedMemorySize,
                         PAIR_SMEM);

    k_stage1 <<<141, 256>>>(h, Wm1, Wa, Wm2, bm2, Wu, bu);
    k_pairout<<<dim3(32, 8), 512, PAIR_SMEM>>>(h, dist, adj, Wm1, bm1,
                                               Wa, ba, Wu, out);
}